// round 9
// baseline (speedup 1.0000x reference)
#include <cuda_runtime.h>
#include <cstdint>

// LDG.64 gather shape: 16 lanes per edge, 2 edges per warp.
// Each warp-level LDG.64 instruction touches exactly 2 x 128B lines
// (one per half-warp) -> avoids the within-LDG multi-wavefront replay
// penalty that capped the LDG.128/LDG.256 variants at ~12M wf x 2.07 cyc.
__global__ __launch_bounds__(256) void edge_dot128_f2_kernel(
    const float* __restrict__ h_user,
    const float* __restrict__ h_item,
    const int* __restrict__ src_clicks,
    const int* __restrict__ dst_clicks,
    const int* __restrict__ src_clickedby,
    const int* __restrict__ dst_clickedby,
    const int* __restrict__ src_follows,
    const int* __restrict__ dst_follows,
    float* __restrict__ out,
    int E)
{
    const int lane = threadIdx.x & 31;
    const int warp_in_block = threadIdx.x >> 5;
    const int sub = lane & 15;       // position within the 16-lane group
    const int group = lane >> 4;     // which of 2 edges this warp handles

    // 16 edges per block (8 warps x 2 edges)
    const int e = blockIdx.x * 16 + warp_in_block * 2 + group;
    const int total = 3 * E;
    if (e >= total) return;

    const float* srcTab;
    const float* dstTab;
    const int* si;
    const int* di;
    int el;
    if (e < E)            { srcTab = h_user; dstTab = h_item; si = src_clicks;    di = dst_clicks;    el = e; }
    else if (e < 2 * E)   { srcTab = h_item; dstTab = h_user; si = src_clickedby; di = dst_clickedby; el = e - E; }
    else                  { srcTab = h_user; dstTab = h_user; si = src_follows;   di = dst_follows;   el = e - 2 * E; }

    // Streaming index loads: read once, evict-first.
    const int s_idx = __ldcs(&si[el]);
    const int d_idx = __ldcs(&di[el]);

    const float2* __restrict__ srow =
        reinterpret_cast<const float2*>(srcTab + (size_t)s_idx * 128);
    const float2* __restrict__ drow =
        reinterpret_cast<const float2*>(dstTab + (size_t)d_idx * 128);

    // Row = 64 float2. This lane covers float2 positions sub, sub+16,
    // sub+32, sub+48 of both rows: 8 independent LDG.64 (MLP=8), each
    // half-warp's 16x8B = one 128B line.
    float2 a0 = __ldg(&srow[sub]);
    float2 b0 = __ldg(&drow[sub]);
    float2 a1 = __ldg(&srow[sub + 16]);
    float2 b1 = __ldg(&drow[sub + 16]);
    float2 a2 = __ldg(&srow[sub + 32]);
    float2 b2 = __ldg(&drow[sub + 32]);
    float2 a3 = __ldg(&srow[sub + 48]);
    float2 b3 = __ldg(&drow[sub + 48]);

    // Two independent accumulation chains.
    float s0 = a0.x * b0.x + a1.x * b1.x + a2.x * b2.x + a3.x * b3.x;
    float s1 = a0.y * b0.y + a1.y * b1.y + a2.y * b2.y + a3.y * b3.y;
    float sum = s0 + s1;

    // Reduce across the 16-lane group (xor masks stay within the group).
    sum += __shfl_xor_sync(0xFFFFFFFFu, sum, 1);
    sum += __shfl_xor_sync(0xFFFFFFFFu, sum, 2);
    sum += __shfl_xor_sync(0xFFFFFFFFu, sum, 4);
    sum += __shfl_xor_sync(0xFFFFFFFFu, sum, 8);

    // Streaming store: don't churn the L2 with output lines.
    if (sub == 0) __stcs(&out[e], sum);
}

extern "C" void kernel_launch(void* const* d_in, const int* in_sizes, int n_in,
                              void* d_out, int out_size)
{
    const float* h_user = (const float*)d_in[0];
    const float* h_item = (const float*)d_in[1];
    const int* src_clicks    = (const int*)d_in[2];
    const int* dst_clicks    = (const int*)d_in[3];
    const int* src_clickedby = (const int*)d_in[4];
    const int* dst_clickedby = (const int*)d_in[5];
    const int* src_follows   = (const int*)d_in[6];
    const int* dst_follows   = (const int*)d_in[7];
    float* out = (float*)d_out;

    const int E = in_sizes[2];  // edges per etype (500000)
    const int total = 3 * E;

    const int threads = 256;            // 8 warps x 2 edges = 16 edges/block
    const int blocks = (total + 15) / 16;

    edge_dot128_f2_kernel<<<blocks, threads>>>(
        h_user, h_item,
        src_clicks, dst_clicks,
        src_clickedby, dst_clickedby,
        src_follows, dst_follows,
        out, E);
}

// round 10
// speedup vs baseline: 1.6351x; 1.6351x over previous
#include <cuda_runtime.h>
#include <cuda_fp16.h>
#include <cstdint>

// fp16 copies of the embedding tables (row = 128 halves = 256B = 16 uint4).
// __device__ globals = allowed scratch; rewritten deterministically each call.
#define N_ROWS_MAX 100000
__device__ uint4 g_user_h[N_ROWS_MAX * 16];
__device__ uint4 g_item_h[N_ROWS_MAX * 16];

// Streaming fp32 -> fp16 conversion: each thread converts one float4 -> 4 halves.
__global__ __launch_bounds__(256) void convert_f32_to_f16_kernel(
    const float4* __restrict__ src, uint2* __restrict__ dst, int n4)
{
    int i = blockIdx.x * blockDim.x + threadIdx.x;
    if (i >= n4) return;
    float4 v = __ldcs(&src[i]);
    __half2 h0 = __floats2half2_rn(v.x, v.y);
    __half2 h1 = __floats2half2_rn(v.z, v.w);
    uint2 o;
    o.x = *reinterpret_cast<unsigned*>(&h0);
    o.y = *reinterpret_cast<unsigned*>(&h1);
    __stcs(&dst[i], o);
}

// Accumulate dot of 8 fp16 pairs (16B vs 16B) into two fp32 chains.
__device__ __forceinline__ void acc16(const uint4& a, const uint4& b,
                                      float2& acc)
{
    const unsigned aw[4] = {a.x, a.y, a.z, a.w};
    const unsigned bw[4] = {b.x, b.y, b.z, b.w};
    #pragma unroll
    for (int i = 0; i < 4; i++) {
        __half2 ha = *reinterpret_cast<const __half2*>(&aw[i]);
        __half2 hb = *reinterpret_cast<const __half2*>(&bw[i]);
        float2 fa = __half22float2(ha);
        float2 fb = __half22float2(hb);
        acc.x = fmaf(fa.x, fb.x, acc.x);
        acc.y = fmaf(fa.y, fb.y, acc.y);
    }
}

// 4 lanes per edge, 8 edges per warp, fp16 rows (256B = 16 x 16B chunks).
// Each lane: chunks {sub, sub+4, sub+8, sub+12} of both rows ->
// 8 independent LDG.128 per thread (MLP=8), 4x16B=64B contiguous per edge
// per warp-instruction. Reduction: 2 shfl_xor within the 4-lane group.
__global__ __launch_bounds__(256) void edge_dot128_h_kernel(
    const int* __restrict__ src_clicks,
    const int* __restrict__ dst_clicks,
    const int* __restrict__ src_clickedby,
    const int* __restrict__ dst_clickedby,
    const int* __restrict__ src_follows,
    const int* __restrict__ dst_follows,
    float* __restrict__ out,
    int E)
{
    const int lane = threadIdx.x & 31;
    const int warp_in_block = threadIdx.x >> 5;
    const int sub = lane & 3;        // position within the 4-lane group
    const int group = lane >> 2;     // which of 8 edges this warp handles

    // 64 edges per block (8 warps x 8 edges)
    const int e = blockIdx.x * 64 + warp_in_block * 8 + group;
    const int total = 3 * E;
    if (e >= total) return;

    const uint4* srcTab;
    const uint4* dstTab;
    const int* si;
    const int* di;
    int el;
    if (e < E)            { srcTab = g_user_h; dstTab = g_item_h; si = src_clicks;    di = dst_clicks;    el = e; }
    else if (e < 2 * E)   { srcTab = g_item_h; dstTab = g_user_h; si = src_clickedby; di = dst_clickedby; el = e - E; }
    else                  { srcTab = g_user_h; dstTab = g_user_h; si = src_follows;   di = dst_follows;   el = e - 2 * E; }

    // Streaming index loads: read once, evict-first.
    const int s_idx = __ldcs(&si[el]);
    const int d_idx = __ldcs(&di[el]);

    const uint4* srow = srcTab + (size_t)s_idx * 16;
    const uint4* drow = dstTab + (size_t)d_idx * 16;

    // 8 independent 16B loads (MLP=8); rows are 256B = 16 chunks of 16B.
    uint4 a0 = __ldg(&srow[sub]);
    uint4 b0 = __ldg(&drow[sub]);
    uint4 a1 = __ldg(&srow[sub + 4]);
    uint4 b1 = __ldg(&drow[sub + 4]);
    uint4 a2 = __ldg(&srow[sub + 8]);
    uint4 b2 = __ldg(&drow[sub + 8]);
    uint4 a3 = __ldg(&srow[sub + 12]);
    uint4 b3 = __ldg(&drow[sub + 12]);

    float2 acc0 = make_float2(0.f, 0.f);
    float2 acc1 = make_float2(0.f, 0.f);
    acc16(a0, b0, acc0);
    acc16(a1, b1, acc1);
    acc16(a2, b2, acc0);
    acc16(a3, b3, acc1);
    float sum = (acc0.x + acc0.y) + (acc1.x + acc1.y);

    // Reduce across the 4-lane group
    sum += __shfl_xor_sync(0xFFFFFFFFu, sum, 1);
    sum += __shfl_xor_sync(0xFFFFFFFFu, sum, 2);

    // Streaming store: don't churn the L2 with output lines.
    if (sub == 0) __stcs(&out[e], sum);
}

extern "C" void kernel_launch(void* const* d_in, const int* in_sizes, int n_in,
                              void* d_out, int out_size)
{
    const float* h_user = (const float*)d_in[0];
    const float* h_item = (const float*)d_in[1];
    const int* src_clicks    = (const int*)d_in[2];
    const int* dst_clicks    = (const int*)d_in[3];
    const int* src_clickedby = (const int*)d_in[4];
    const int* dst_clickedby = (const int*)d_in[5];
    const int* src_follows   = (const int*)d_in[6];
    const int* dst_follows   = (const int*)d_in[7];
    float* out = (float*)d_out;

    const int E = in_sizes[2];          // edges per etype (500000)
    const int total = 3 * E;

    // --- Pass 1: fp32 -> fp16 table conversion (deterministic every call) ---
    {
        uint4* gu = nullptr; uint4* gi = nullptr;
        cudaGetSymbolAddress((void**)&gu, g_user_h);
        cudaGetSymbolAddress((void**)&gi, g_item_h);
        const int n4u = in_sizes[0] / 4;   // float4 count, user table
        const int n4i = in_sizes[1] / 4;   // float4 count, item table
        convert_f32_to_f16_kernel<<<(n4u + 255) / 256, 256>>>(
            (const float4*)h_user, (uint2*)gu, n4u);
        convert_f32_to_f16_kernel<<<(n4i + 255) / 256, 256>>>(
            (const float4*)h_item, (uint2*)gi, n4i);
    }

    // --- Pass 2: fused edge dot products on fp16 tables ---
    const int threads = 256;            // 8 warps x 8 edges = 64 edges/block
    const int blocks = (total + 63) / 64;
    edge_dot128_h_kernel<<<blocks, threads>>>(
        src_clicks, dst_clicks,
        src_clickedby, dst_clickedby,
        src_follows, dst_follows,
        out, E);
}

// round 11
// speedup vs baseline: 1.6454x; 1.0063x over previous
#include <cuda_runtime.h>
#include <cuda_fp16.h>
#include <cstdint>

// fp16 copies of the embedding tables (row = 128 halves = 256B = 16 uint4).
// __device__ globals = allowed scratch; rewritten deterministically each call.
#define N_ROWS_MAX 100000
__device__ uint4 g_user_h[N_ROWS_MAX * 16];
__device__ uint4 g_item_h[N_ROWS_MAX * 16];

static __device__ __forceinline__ unsigned h2bits(__half2 h)
{
    return *reinterpret_cast<unsigned*>(&h);
}

// Wide streaming fp32 -> fp16: each thread reads 2 x float4 (32B), writes
// 1 x uint4 (16B).
__global__ __launch_bounds__(256) void convert_f32_to_f16_kernel(
    const float4* __restrict__ src, uint4* __restrict__ dst, int n8)
{
    int i = blockIdx.x * blockDim.x + threadIdx.x;
    if (i >= n8) return;
    float4 v0 = __ldcs(&src[2 * i]);
    float4 v1 = __ldcs(&src[2 * i + 1]);
    uint4 o;
    o.x = h2bits(__floats2half2_rn(v0.x, v0.y));
    o.y = h2bits(__floats2half2_rn(v0.z, v0.w));
    o.z = h2bits(__floats2half2_rn(v1.x, v1.y));
    o.w = h2bits(__floats2half2_rn(v1.z, v1.w));
    __stcs(&dst[i], o);
}

// Accumulate dot of 8 fp16 pairs (16B vs 16B) into two fp32 chains.
__device__ __forceinline__ void acc16(const uint4& a, const uint4& b,
                                      float2& acc)
{
    const unsigned aw[4] = {a.x, a.y, a.z, a.w};
    const unsigned bw[4] = {b.x, b.y, b.z, b.w};
    #pragma unroll
    for (int i = 0; i < 4; i++) {
        __half2 ha = *reinterpret_cast<const __half2*>(&aw[i]);
        __half2 hb = *reinterpret_cast<const __half2*>(&bw[i]);
        float2 fa = __half22float2(ha);
        float2 fb = __half22float2(hb);
        acc.x = fmaf(fa.x, fb.x, acc.x);
        acc.y = fmaf(fa.y, fb.y, acc.y);
    }
}

// Generic single-etype scorer: 4 lanes per edge, 8 edges per warp, fp16 rows
// (256B = 16 x 16B chunks). Each lane: chunks {sub, sub+4, sub+8, sub+12} of
// both rows -> 8 independent LDG.128 per thread (MLP=8).
__global__ __launch_bounds__(256) void edge_dot_h_kernel(
    const uint4* __restrict__ srcTab, const int* __restrict__ si,
    const uint4* __restrict__ dstTab, const int* __restrict__ di,
    float* __restrict__ out, int E)
{
    const int lane = threadIdx.x & 31;
    const int warp_in_block = threadIdx.x >> 5;
    const int sub = lane & 3;
    const int group = lane >> 2;

    const int e = blockIdx.x * 64 + warp_in_block * 8 + group;
    if (e >= E) return;

    const int s_idx = __ldcs(&si[e]);
    const int d_idx = __ldcs(&di[e]);

    const uint4* srow = srcTab + (size_t)s_idx * 16;
    const uint4* drow = dstTab + (size_t)d_idx * 16;

    uint4 a0 = __ldg(&srow[sub]);
    uint4 b0 = __ldg(&drow[sub]);
    uint4 a1 = __ldg(&srow[sub + 4]);
    uint4 b1 = __ldg(&drow[sub + 4]);
    uint4 a2 = __ldg(&srow[sub + 8]);
    uint4 b2 = __ldg(&drow[sub + 8]);
    uint4 a3 = __ldg(&srow[sub + 12]);
    uint4 b3 = __ldg(&drow[sub + 12]);

    float2 acc0 = make_float2(0.f, 0.f);
    float2 acc1 = make_float2(0.f, 0.f);
    acc16(a0, b0, acc0);
    acc16(a1, b1, acc1);
    acc16(a2, b2, acc0);
    acc16(a3, b3, acc1);
    float sum = (acc0.x + acc0.y) + (acc1.x + acc1.y);

    sum += __shfl_xor_sync(0xFFFFFFFFu, sum, 1);
    sum += __shfl_xor_sync(0xFFFFFFFFu, sum, 2);

    if (sub == 0) __stcs(&out[e], sum);
}

extern "C" void kernel_launch(void* const* d_in, const int* in_sizes, int n_in,
                              void* d_out, int out_size)
{
    const float* h_user = (const float*)d_in[0];
    const float* h_item = (const float*)d_in[1];
    const int* src_clicks    = (const int*)d_in[2];
    const int* dst_clicks    = (const int*)d_in[3];
    const int* src_clickedby = (const int*)d_in[4];
    const int* dst_clickedby = (const int*)d_in[5];
    const int* src_follows   = (const int*)d_in[6];
    const int* dst_follows   = (const int*)d_in[7];
    float* out = (float*)d_out;

    const int E = in_sizes[2];          // edges per etype (500000)

    // Host-side stream/event objects, created once on the first (non-capture)
    // call. Not device memory; legal.
    static cudaStream_t s1 = nullptr;
    static cudaEvent_t ev_user = nullptr, ev_follows = nullptr;
    if (!s1) {
        cudaStreamCreateWithFlags(&s1, cudaStreamNonBlocking);
        cudaEventCreateWithFlags(&ev_user, cudaEventDisableTiming);
        cudaEventCreateWithFlags(&ev_follows, cudaEventDisableTiming);
    }

    uint4* gu = nullptr; uint4* gi = nullptr;
    cudaGetSymbolAddress((void**)&gu, g_user_h);
    cudaGetSymbolAddress((void**)&gi, g_item_h);
    const int n8u = in_sizes[0] / 8;
    const int n8i = in_sizes[1] / 8;

    const int sthreads = 256;
    const int sblocks = (E + 63) / 64;  // 64 edges per block

    // 1) Convert user table (origin stream).
    convert_f32_to_f16_kernel<<<(n8u + 255) / 256, 256>>>(
        (const float4*)h_user, gu, n8u);

    // 2) Fork: follows (user-only) on s1, overlapped with convert_item.
    cudaEventRecord(ev_user, 0);
    cudaStreamWaitEvent(s1, ev_user, 0);
    edge_dot_h_kernel<<<sblocks, sthreads, 0, s1>>>(
        gu, src_follows, gu, dst_follows, out + 2 * (size_t)E, E);
    cudaEventRecord(ev_follows, s1);

    // 3) Convert item table (origin stream), then clicks / clickedby.
    convert_f32_to_f16_kernel<<<(n8i + 255) / 256, 256>>>(
        (const float4*)h_item, gi, n8i);
    edge_dot_h_kernel<<<sblocks, sthreads>>>(
        gu, src_clicks, gi, dst_clicks, out, E);
    edge_dot_h_kernel<<<sblocks, sthreads>>>(
        gi, src_clickedby, gu, dst_clickedby, out + (size_t)E, E);

    // 4) Join the fork back into the origin stream.
    cudaStreamWaitEvent(0, ev_follows, 0);
}